// round 3
// baseline (speedup 1.0000x reference)
#include <cuda_runtime.h>
#include <math.h>

#define S_LEN   2048
#define HID     2048
#define NH      32
#define NKV     8
#define HD      64
#define BATCH   2
#define M_ROWS  (BATCH * S_LEN)      // 4096
#define NQCOLS  (NH * HD)            // 2048
#define NKCOLS  (NKV * HD)           // 512
#define N_TOT   (NQCOLS + 2 * NKCOLS) // 3072

// ---------------- scratch (static __device__ arrays; no allocation) ----------
__device__ float g_qkv[M_ROWS * N_TOT];           // raw QKV projections
__device__ float g_q[BATCH * NH  * S_LEN * HD];   // [b][h][s][d]
__device__ float g_k[BATCH * NKV * S_LEN * HD];   // [b][hk][s][d]
__device__ float g_v[BATCH * NKV * S_LEN * HD];   // [b][hk][s][d]
__device__ float g_ao[M_ROWS * NQCOLS];           // attention out [b*s][h*d]

// ---------------- fp32 GEMM: C[M][N] = A[M][K] @ B[K][N] ---------------------
// BM=BN=128, BK=8, 256 threads, 8x8 microtile (split 2x4 / 2x4), double-buffered.
// M, N multiples of 128; K multiple of 8.
__global__ void __launch_bounds__(256) sgemm128(
    const float* __restrict__ A, int lda,
    const float* __restrict__ B, int ldb,
    float* __restrict__ C, int ldc, int K)
{
    __shared__ float As[2][8][132];   // As[buf][k][m] (padded: k-stride 132 avoids write conflicts)
    __shared__ float Bs[2][8][128];   // Bs[buf][k][n]

    const int tid = threadIdx.x;
    const int tx = tid & 15;          // n microtile
    const int ty = tid >> 4;          // m microtile
    const int m0 = blockIdx.y * 128;
    const int n0 = blockIdx.x * 128;

    // A tile load: 128 rows x 8 k, 2 threads/row (float4 each)
    const int am = tid >> 1;
    const int ak = (tid & 1) << 2;
    // B tile load: 8 rows x 128 n, 32 threads/row (float4 each)
    const int bk = tid >> 5;
    const int bn = (tid & 31) << 2;

    const float* Ap = A + (size_t)(m0 + am) * lda + ak;
    const float* Bp = B + (size_t)bk * ldb + n0 + bn;

    float acc[8][8] = {};

    // preload tile 0
    {
        float4 a = *(const float4*)(Ap);
        float4 bb = *(const float4*)(Bp);
        As[0][ak + 0][am] = a.x;
        As[0][ak + 1][am] = a.y;
        As[0][ak + 2][am] = a.z;
        As[0][ak + 3][am] = a.w;
        *(float4*)&Bs[0][bk][bn] = bb;
    }
    __syncthreads();

    const int KT = K >> 3;
    int cur = 0;
    for (int kt = 0; kt < KT; kt++) {
        float4 a_nx, b_nx;
        const bool has_next = (kt + 1 < KT);
        if (has_next) {
            a_nx = *(const float4*)(Ap + (kt + 1) * 8);
            b_nx = *(const float4*)(Bp + (size_t)(kt + 1) * 8 * ldb);
        }
#pragma unroll
        for (int kk = 0; kk < 8; kk++) {
            float4 a0 = *(const float4*)&As[cur][kk][ty << 2];
            float4 a1 = *(const float4*)&As[cur][kk][64 + (ty << 2)];
            float4 b0 = *(const float4*)&Bs[cur][kk][tx << 2];
            float4 b1 = *(const float4*)&Bs[cur][kk][64 + (tx << 2)];
            float av[8] = {a0.x, a0.y, a0.z, a0.w, a1.x, a1.y, a1.z, a1.w};
            float bv[8] = {b0.x, b0.y, b0.z, b0.w, b1.x, b1.y, b1.z, b1.w};
#pragma unroll
            for (int i = 0; i < 8; i++)
#pragma unroll
                for (int j = 0; j < 8; j++)
                    acc[i][j] += av[i] * bv[j];
        }
        if (has_next) {
            int nxt = cur ^ 1;
            As[nxt][ak + 0][am] = a_nx.x;
            As[nxt][ak + 1][am] = a_nx.y;
            As[nxt][ak + 2][am] = a_nx.z;
            As[nxt][ak + 3][am] = a_nx.w;
            *(float4*)&Bs[nxt][bk][bn] = b_nx;
            cur = nxt;
        }
        __syncthreads();
    }

#pragma unroll
    for (int i = 0; i < 8; i++) {
        int r = (i < 4) ? ((ty << 2) + i) : (64 + (ty << 2) + (i - 4));
        float4 c0 = make_float4(acc[i][0], acc[i][1], acc[i][2], acc[i][3]);
        float4 c1 = make_float4(acc[i][4], acc[i][5], acc[i][6], acc[i][7]);
        *(float4*)&C[(size_t)(m0 + r) * ldc + n0 + (tx << 2)] = c0;
        *(float4*)&C[(size_t)(m0 + r) * ldc + n0 + 64 + (tx << 2)] = c1;
    }
}

// ---------------- RoPE + transpose/scatter -----------------------------------
__global__ void __launch_bounds__(256) rope_kernel(
    const float* __restrict__ cosp, const float* __restrict__ sinp)
{
    int idx = blockIdx.x * 256 + threadIdx.x;   // [0, M_ROWS*N_TOT)
    int m = idx / N_TOT;
    int n = idx - m * N_TOT;
    float val = g_qkv[idx];
    int b = m >> 11;
    int s = m & (S_LEN - 1);

    if (n < NQCOLS) {
        int d = n & 63, hh = n >> 6;
        float pv = g_qkv[(size_t)m * N_TOT + (n ^ 32)];
        float rot = (d < 32) ? -pv : pv;
        float cs = cosp[(size_t)m * HD + d];
        float sn = sinp[(size_t)m * HD + d];
        g_q[(((size_t)(b * NH + hh)) * S_LEN + s) * HD + d] = val * cs + rot * sn;
    } else if (n < NQCOLS + NKCOLS) {
        int nn = n - NQCOLS;
        int d = nn & 63, hh = nn >> 6;
        float pv = g_qkv[(size_t)m * N_TOT + (n ^ 32)];
        float rot = (d < 32) ? -pv : pv;
        float cs = cosp[(size_t)m * HD + d];
        float sn = sinp[(size_t)m * HD + d];
        g_k[(((size_t)(b * NKV + hh)) * S_LEN + s) * HD + d] = val * cs + rot * sn;
    } else {
        int nn = n - NQCOLS - NKCOLS;
        int d = nn & 63, hh = nn >> 6;
        g_v[(((size_t)(b * NKV + hh)) * S_LEN + s) * HD + d] = val;
    }
}

// ---------------- flash attention (fp32, online softmax) ---------------------
#define QK_LD 68   // padded (float4-aligned: 68*4 = 272)
#define PS_LD 65

#define ATTN_SMEM_FLOATS (64 * QK_LD * 2 + 64 * PS_LD + 64 * 64 + 3 * 64)

__global__ void __launch_bounds__(256) attn_kernel(
    const float* __restrict__ q, const float* __restrict__ k,
    const float* __restrict__ v, float* __restrict__ ao)
{
    extern __shared__ float sm[];
    float* Qs   = sm;                       // [64][68] d-major: Qs[d][r]
    float* Ks   = Qs + 64 * QK_LD;          // [64][68] d-major: Ks[d][c]
    float* Ps   = Ks + 64 * QK_LD;          // [64][65] Ps[r][c]
    float* Vs   = Ps + 64 * PS_LD;          // [64][64] Vs[c][d]
    float* rowm = Vs + 64 * 64;
    float* rowl = rowm + 64;
    float* corr = rowl + 64;

    const int tid = threadIdx.x;
    const int tx = tid & 15;
    const int ty = tid >> 4;
    const int qb = gridDim.x - 1 - blockIdx.x;   // long blocks first
    const int h  = blockIdx.y;
    const int b  = blockIdx.z;
    const int hk = h >> 2;                        // GQA group of 4

    const float* qptr  = q + (((size_t)(b * NH + h)) * S_LEN + qb * 64) * HD;
    const float* kbase = k + ((size_t)(b * NKV + hk)) * S_LEN * HD;
    const float* vbase = v + ((size_t)(b * NKV + hk)) * S_LEN * HD;

    const int lrow = tid >> 2;          // 0..63
    const int lc4  = (tid & 3) << 2;    // 0,4,8,12

    // load Q transposed, pre-scaled by 1/sqrt(64)
#pragma unroll
    for (int dd = 0; dd < 64; dd += 16) {
        float4 t = *(const float4*)&qptr[lrow * 64 + dd + lc4];
        int d = dd + lc4;
        Qs[(d + 0) * QK_LD + lrow] = t.x * 0.125f;
        Qs[(d + 1) * QK_LD + lrow] = t.y * 0.125f;
        Qs[(d + 2) * QK_LD + lrow] = t.z * 0.125f;
        Qs[(d + 3) * QK_LD + lrow] = t.w * 0.125f;
    }
    if (tid < 64) { rowm[tid] = -1e30f; rowl[tid] = 0.f; }

    float o[4][4] = {};

    for (int kb = 0; kb <= qb; kb++) {
        __syncthreads();   // previous iteration done reading Ks/Vs/Ps
        const float* kp = kbase + (size_t)kb * 64 * HD;
        const float* vp = vbase + (size_t)kb * 64 * HD;
#pragma unroll
        for (int dd = 0; dd < 64; dd += 16) {
            float4 t = *(const float4*)&kp[lrow * 64 + dd + lc4];
            int d = dd + lc4;
            Ks[(d + 0) * QK_LD + lrow] = t.x;
            Ks[(d + 1) * QK_LD + lrow] = t.y;
            Ks[(d + 2) * QK_LD + lrow] = t.z;
            Ks[(d + 3) * QK_LD + lrow] = t.w;
            float4 tv = *(const float4*)&vp[lrow * 64 + dd + lc4];
            *(float4*)&Vs[lrow * 64 + dd + lc4] = tv;
        }
        __syncthreads();

        // S = (Q/8) K^T
        float sacc[4][4] = {};
#pragma unroll 16
        for (int d = 0; d < 64; d++) {
            float4 av = *(const float4*)&Qs[d * QK_LD + (ty << 2)];
            float4 bv = *(const float4*)&Ks[d * QK_LD + (tx << 2)];
            float aa[4] = {av.x, av.y, av.z, av.w};
            float bb[4] = {bv.x, bv.y, bv.z, bv.w};
#pragma unroll
            for (int i = 0; i < 4; i++)
#pragma unroll
                for (int j = 0; j < 4; j++)
                    sacc[i][j] += aa[i] * bb[j];
        }
        const bool diag = (kb == qb);
#pragma unroll
        for (int i = 0; i < 4; i++) {
            int r = (ty << 2) + i;
#pragma unroll
            for (int j = 0; j < 4; j++) {
                int c = (tx << 2) + j;
                float sv = sacc[i][j];
                if (diag && c > r) sv = -1e30f;
                Ps[r * PS_LD + c] = sv;
            }
        }
        __syncthreads();

        // online softmax: 4 threads per row, shuffle reductions within 4-lane group
        {
            const int r  = tid >> 2;          // 0..63
            const int c0 = (tid & 3) << 4;    // 16 cols per thread
            float rm = -1e30f;
#pragma unroll
            for (int j = 0; j < 16; j++) rm = fmaxf(rm, Ps[r * PS_LD + c0 + j]);
            float mold = rowm[r];             // all 4 lanes read BEFORE shuffles
            rm = fmaxf(rm, mold);
            rm = fmaxf(rm, __shfl_xor_sync(0xffffffffu, rm, 1));
            rm = fmaxf(rm, __shfl_xor_sync(0xffffffffu, rm, 2));
            float sum = 0.f;
#pragma unroll
            for (int j = 0; j < 16; j++) {
                float p = __expf(Ps[r * PS_LD + c0 + j] - rm);
                Ps[r * PS_LD + c0 + j] = p;
                sum += p;
            }
            sum += __shfl_xor_sync(0xffffffffu, sum, 1);
            sum += __shfl_xor_sync(0xffffffffu, sum, 2);
            if ((tid & 3) == 0) {             // after shuffles -> lanes 1-3 already read rowm/rowl
                float co = __expf(mold - rm);
                rowl[r] = rowl[r] * co + sum;
                rowm[r] = rm;
                corr[r] = co;
            }
        }
        __syncthreads();

        // O = O*corr + P V
#pragma unroll
        for (int i = 0; i < 4; i++) {
            float co = corr[(ty << 2) + i];
#pragma unroll
            for (int j = 0; j < 4; j++) o[i][j] *= co;
        }
#pragma unroll 8
        for (int c = 0; c < 64; c++) {
            float4 vv = *(const float4*)&Vs[c * 64 + (tx << 2)];
            float p0 = Ps[((ty << 2) + 0) * PS_LD + c];
            float p1 = Ps[((ty << 2) + 1) * PS_LD + c];
            float p2 = Ps[((ty << 2) + 2) * PS_LD + c];
            float p3 = Ps[((ty << 2) + 3) * PS_LD + c];
            o[0][0] += p0 * vv.x; o[0][1] += p0 * vv.y; o[0][2] += p0 * vv.z; o[0][3] += p0 * vv.w;
            o[1][0] += p1 * vv.x; o[1][1] += p1 * vv.y; o[1][2] += p1 * vv.z; o[1][3] += p1 * vv.w;
            o[2][0] += p2 * vv.x; o[2][1] += p2 * vv.y; o[2][2] += p2 * vv.z; o[2][3] += p2 * vv.w;
            o[3][0] += p3 * vv.x; o[3][1] += p3 * vv.y; o[3][2] += p3 * vv.z; o[3][3] += p3 * vv.w;
        }
    }

    // epilogue: divide by l, write [b][s][h*64+d]
#pragma unroll
    for (int i = 0; i < 4; i++) {
        int r = (ty << 2) + i;
        float inv = 1.0f / rowl[r];
        float4 res = make_float4(o[i][0] * inv, o[i][1] * inv, o[i][2] * inv, o[i][3] * inv);
        int s = qb * 64 + r;
        *(float4*)&ao[((size_t)(b * S_LEN + s)) * NQCOLS + h * 64 + (tx << 2)] = res;
    }
}

// ---------------- launch ------------------------------------------------------
extern "C" void kernel_launch(void* const* d_in, const int* in_sizes, int n_in,
                              void* d_out, int out_size)
{
    const float* hidden = (const float*)d_in[0];
    // d_in[1] = attention_mask: exactly causal(-1e9) -> implemented directly, unused
    const float* cosp = (const float*)d_in[2];
    const float* sinp = (const float*)d_in[3];
    const float* Wq = (const float*)d_in[4];
    const float* Wk = (const float*)d_in[5];
    const float* Wv = (const float*)d_in[6];
    const float* Wo = (const float*)d_in[7];
    float* out = (float*)d_out;

    float *qkv, *qp, *kp, *vp, *ao;
    cudaGetSymbolAddress((void**)&qkv, g_qkv);
    cudaGetSymbolAddress((void**)&qp, g_q);
    cudaGetSymbolAddress((void**)&kp, g_k);
    cudaGetSymbolAddress((void**)&vp, g_v);
    cudaGetSymbolAddress((void**)&ao, g_ao);

    const int attn_smem = ATTN_SMEM_FLOATS * (int)sizeof(float);
    cudaFuncSetAttribute(attn_kernel, cudaFuncAttributeMaxDynamicSharedMemorySize, attn_smem);

    // QKV projections into fused scratch [4096][3072]
    sgemm128<<<dim3(NQCOLS / 128, M_ROWS / 128), 256>>>(hidden, HID, Wq, NQCOLS, qkv,                    N_TOT, HID);
    sgemm128<<<dim3(NKCOLS / 128, M_ROWS / 128), 256>>>(hidden, HID, Wk, NKCOLS, qkv + NQCOLS,           N_TOT, HID);
    sgemm128<<<dim3(NKCOLS / 128, M_ROWS / 128), 256>>>(hidden, HID, Wv, NKCOLS, qkv + NQCOLS + NKCOLS,  N_TOT, HID);

    // RoPE + transpose/scatter
    rope_kernel<<<(M_ROWS * N_TOT) / 256, 256>>>(cosp, sinp);

    // causal flash attention
    attn_kernel<<<dim3(S_LEN / 64, NH, BATCH), 256, attn_smem>>>(qp, kp, vp, ao);

    // output projection -> d_out
    sgemm128<<<dim3(HID / 128, M_ROWS / 128), 256>>>(ao, NQCOLS, Wo, HID, out, HID, NQCOLS);
}

// round 5
// speedup vs baseline: 1.4403x; 1.4403x over previous
#include <cuda_runtime.h>
#include <cuda_bf16.h>
#include <math.h>

#define S_LEN   2048
#define HID     2048
#define NH      32
#define NKV     8
#define HD      64
#define BATCH   2
#define M_ROWS  (BATCH * S_LEN)       // 4096
#define NQCOLS  (NH * HD)             // 2048
#define NKCOLS  (NKV * HD)            // 512
#define N_TOT   (NQCOLS + 2 * NKCOLS) // 3072

typedef __nv_bfloat16 bf16;

// ---------------- scratch (static __device__ arrays; no allocation) ----------
__device__ float g_qkv[M_ROWS * N_TOT];
__device__ float g_q[BATCH * NH  * S_LEN * HD];
__device__ float g_k[BATCH * NKV * S_LEN * HD];
__device__ float g_v[BATCH * NKV * S_LEN * HD];
__device__ float g_ao[M_ROWS * NQCOLS];

// split-bf16 operands
__device__ bf16 g_ahi[M_ROWS * HID],   g_alo[M_ROWS * HID];     // hidden
__device__ bf16 g_wqhi[NQCOLS * HID],  g_wqlo[NQCOLS * HID];    // Wq^T [N][K]
__device__ bf16 g_wkhi[NKCOLS * HID],  g_wklo[NKCOLS * HID];    // Wk^T
__device__ bf16 g_wvhi[NKCOLS * HID],  g_wvlo[NKCOLS * HID];    // Wv^T
__device__ bf16 g_wohi[HID * NQCOLS],  g_wolo[HID * NQCOLS];    // Wo^T [N=HID][K=NQCOLS]
__device__ bf16 g_aohi[M_ROWS * NQCOLS], g_aolo[M_ROWS * NQCOLS];

// ---------------- split conversion (elementwise, row-major preserved) --------
__global__ void __launch_bounds__(256) convert_split(
    const float* __restrict__ src, bf16* __restrict__ hi, bf16* __restrict__ lo, int n4)
{
    int i = blockIdx.x * 256 + threadIdx.x;
    if (i >= n4) return;
    float4 v = ((const float4*)src)[i];
    bf16 h0 = __float2bfloat16(v.x), h1 = __float2bfloat16(v.y);
    bf16 h2 = __float2bfloat16(v.z), h3 = __float2bfloat16(v.w);
    bf16 l0 = __float2bfloat16(v.x - __bfloat162float(h0));
    bf16 l1 = __float2bfloat16(v.y - __bfloat162float(h1));
    bf16 l2 = __float2bfloat16(v.z - __bfloat162float(h2));
    bf16 l3 = __float2bfloat16(v.w - __bfloat162float(h3));
    ((__nv_bfloat162*)hi)[2*i]   = __halves2bfloat162(h0, h1);
    ((__nv_bfloat162*)hi)[2*i+1] = __halves2bfloat162(h2, h3);
    ((__nv_bfloat162*)lo)[2*i]   = __halves2bfloat162(l0, l1);
    ((__nv_bfloat162*)lo)[2*i+1] = __halves2bfloat162(l2, l3);
}

// ---------------- transpose + split: W[K][N] fp32 -> T[N][K] bf16 hi/lo ------
__global__ void __launch_bounds__(256) transpose_split(
    const float* __restrict__ W, bf16* __restrict__ Thi, bf16* __restrict__ Tlo,
    int Kdim, int Ndim)
{
    __shared__ float tile[32][33];
    int nx = blockIdx.x * 32, ky = blockIdx.y * 32;
    int tx = threadIdx.x, ty = threadIdx.y;   // block (32,8)
#pragma unroll
    for (int j = 0; j < 4; j++)
        tile[ty + j*8][tx] = W[(size_t)(ky + ty + j*8) * Ndim + nx + tx];
    __syncthreads();
#pragma unroll
    for (int j = 0; j < 4; j++) {
        float v = tile[tx][ty + j*8];
        bf16 h = __float2bfloat16(v);
        bf16 l = __float2bfloat16(v - __bfloat162float(h));
        size_t o = (size_t)(nx + ty + j*8) * Kdim + ky + tx;
        Thi[o] = h;
        Tlo[o] = l;
    }
}

// ---------------- split-bf16 tensor-core GEMM --------------------------------
// C[M][N] = Ahi·Bhi^T + Ahi·Blo^T + Alo·Bhi^T  (A [M][K], B given as [N][K])
// BM=BN=128, BK=32, 256 threads, warp tile 64x32, cp.async double buffer.
#define GP    40                  // padded smem row stride (halves)
#define GTILE (128 * GP)          // halves per array tile

__device__ __forceinline__ void mma_bf16(float* c, const unsigned* a, const unsigned* b) {
    asm volatile(
        "mma.sync.aligned.m16n8k16.row.col.f32.bf16.bf16.f32 "
        "{%0,%1,%2,%3}, {%4,%5,%6,%7}, {%8,%9}, {%0,%1,%2,%3};"
        : "+f"(c[0]), "+f"(c[1]), "+f"(c[2]), "+f"(c[3])
        : "r"(a[0]), "r"(a[1]), "r"(a[2]), "r"(a[3]), "r"(b[0]), "r"(b[1]));
}

__device__ __forceinline__ void cp16(unsigned dst, const void* src) {
    asm volatile("cp.async.cg.shared.global [%0], [%1], 16;" :: "r"(dst), "l"(src));
}

__global__ void __launch_bounds__(256) gemm_bf16split(
    const bf16* __restrict__ Ahi, const bf16* __restrict__ Alo,
    const bf16* __restrict__ Bhi, const bf16* __restrict__ Blo,
    float* __restrict__ C, int K, int ldc)
{
    extern __shared__ bf16 sm[];
    const int tid = threadIdx.x;
    const int m0 = blockIdx.y * 128;
    const int n0 = blockIdx.x * 128;

    const unsigned sbase = (unsigned)__cvta_generic_to_shared(sm);
    const int lrow = tid >> 1;
    const int lq   = (tid & 1) * 16;      // half-offset within 32-half row

    const bf16* gAh = Ahi + (size_t)(m0 + lrow) * K + lq;
    const bf16* gAl = Alo + (size_t)(m0 + lrow) * K + lq;
    const bf16* gBh = Bhi + (size_t)(n0 + lrow) * K + lq;
    const bf16* gBl = Blo + (size_t)(n0 + lrow) * K + lq;
    const unsigned dsm = sbase + (unsigned)(lrow * GP + lq) * 2;
    const unsigned ARR = GTILE * 2;       // bytes per array tile
    const unsigned BUF = 4 * ARR;         // bytes per buffer

    const int lane = tid & 31;
    const int wid  = tid >> 5;
    const int wm = (wid & 1) << 6;        // 0 / 64
    const int wn = (wid >> 1) << 5;       // 0 / 32 / 64 / 96
    const int g = lane >> 2, t = lane & 3;

    float acc[4][4][4];
#pragma unroll
    for (int i = 0; i < 4; i++)
#pragma unroll
        for (int j = 0; j < 4; j++)
#pragma unroll
            for (int r = 0; r < 4; r++) acc[i][j][r] = 0.f;

    const int KT = K >> 5;

    // prologue: tile 0 -> buf 0
    {
        unsigned d = dsm;
        cp16(d + 0*ARR, gAh);      cp16(d + 0*ARR + 16, gAh + 8);
        cp16(d + 1*ARR, gAl);      cp16(d + 1*ARR + 16, gAl + 8);
        cp16(d + 2*ARR, gBh);      cp16(d + 2*ARR + 16, gBh + 8);
        cp16(d + 3*ARR, gBl);      cp16(d + 3*ARR + 16, gBl + 8);
        asm volatile("cp.async.commit_group;");
    }

    for (int kt = 0; kt < KT; kt++) {
        const int buf = kt & 1;
        if (kt + 1 < KT) {
            const int k0 = (kt + 1) << 5;
            unsigned d = dsm + (buf ^ 1) * BUF;
            cp16(d + 0*ARR, gAh + k0);  cp16(d + 0*ARR + 16, gAh + k0 + 8);
            cp16(d + 1*ARR, gAl + k0);  cp16(d + 1*ARR + 16, gAl + k0 + 8);
            cp16(d + 2*ARR, gBh + k0);  cp16(d + 2*ARR + 16, gBh + k0 + 8);
            cp16(d + 3*ARR, gBl + k0);  cp16(d + 3*ARR + 16, gBl + k0 + 8);
            asm volatile("cp.async.commit_group;");
            asm volatile("cp.async.wait_group 1;");
        } else {
            asm volatile("cp.async.wait_group 0;");
        }
        __syncthreads();

        const bf16* sAh = sm + (size_t)buf * 4 * GTILE;
        const bf16* sAl = sAh + GTILE;
        const bf16* sBh = sAl + GTILE;
        const bf16* sBl = sBh + GTILE;

#pragma unroll
        for (int s = 0; s < 2; s++) {
            const int kc = s * 16;
            unsigned ah[4][4], al[4][4];
#pragma unroll
            for (int mt = 0; mt < 4; mt++) {
                const int r = wm + mt * 16;
                ah[mt][0] = *(const unsigned*)&sAh[(r + g    ) * GP + kc + 2*t    ];
                ah[mt][1] = *(const unsigned*)&sAh[(r + g + 8) * GP + kc + 2*t    ];
                ah[mt][2] = *(const unsigned*)&sAh[(r + g    ) * GP + kc + 2*t + 8];
                ah[mt][3] = *(const unsigned*)&sAh[(r + g + 8) * GP + kc + 2*t + 8];
                al[mt][0] = *(const unsigned*)&sAl[(r + g    ) * GP + kc + 2*t    ];
                al[mt][1] = *(const unsigned*)&sAl[(r + g + 8) * GP + kc + 2*t    ];
                al[mt][2] = *(const unsigned*)&sAl[(r + g    ) * GP + kc + 2*t + 8];
                al[mt][3] = *(const unsigned*)&sAl[(r + g + 8) * GP + kc + 2*t + 8];
            }
            unsigned bh[4][2], bl[4][2];
#pragma unroll
            for (int nt = 0; nt < 4; nt++) {
                const int r = wn + nt * 8 + g;
                bh[nt][0] = *(const unsigned*)&sBh[r * GP + kc + 2*t    ];
                bh[nt][1] = *(const unsigned*)&sBh[r * GP + kc + 2*t + 8];
                bl[nt][0] = *(const unsigned*)&sBl[r * GP + kc + 2*t    ];
                bl[nt][1] = *(const unsigned*)&sBl[r * GP + kc + 2*t + 8];
            }
#pragma unroll
            for (int mt = 0; mt < 4; mt++)
#pragma unroll
                for (int nt = 0; nt < 4; nt++) {
                    mma_bf16(acc[mt][nt], ah[mt], bh[nt]);
                    mma_bf16(acc[mt][nt], ah[mt], bl[nt]);
                    mma_bf16(acc[mt][nt], al[mt], bh[nt]);
                }
        }
        __syncthreads();
    }

    // epilogue
#pragma unroll
    for (int mt = 0; mt < 4; mt++)
#pragma unroll
        for (int nt = 0; nt < 4; nt++) {
            const int r = m0 + wm + mt * 16 + g;
            const int c = n0 + wn + nt * 8 + 2 * t;
            *(float2*)&C[(size_t)r * ldc + c]       = make_float2(acc[mt][nt][0], acc[mt][nt][1]);
            *(float2*)&C[(size_t)(r + 8) * ldc + c] = make_float2(acc[mt][nt][2], acc[mt][nt][3]);
        }
}

#define GEMM_SMEM (2 * 4 * GTILE * 2)   // 81920 bytes

// ---------------- RoPE + transpose/scatter -----------------------------------
__global__ void __launch_bounds__(256) rope_kernel(
    const float* __restrict__ cosp, const float* __restrict__ sinp)
{
    int idx = blockIdx.x * 256 + threadIdx.x;
    int m = idx / N_TOT;
    int n = idx - m * N_TOT;
    float val = g_qkv[idx];
    int b = m >> 11;
    int s = m & (S_LEN - 1);

    if (n < NQCOLS) {
        int d = n & 63, hh = n >> 6;
        float pv = g_qkv[(size_t)m * N_TOT + (n ^ 32)];
        float rot = (d < 32) ? -pv : pv;
        float cs = cosp[(size_t)m * HD + d];
        float sn = sinp[(size_t)m * HD + d];
        g_q[(((size_t)(b * NH + hh)) * S_LEN + s) * HD + d] = val * cs + rot * sn;
    } else if (n < NQCOLS + NKCOLS) {
        int nn = n - NQCOLS;
        int d = nn & 63, hh = nn >> 6;
        float pv = g_qkv[(size_t)m * N_TOT + (n ^ 32)];
        float rot = (d < 32) ? -pv : pv;
        float cs = cosp[(size_t)m * HD + d];
        float sn = sinp[(size_t)m * HD + d];
        g_k[(((size_t)(b * NKV + hh)) * S_LEN + s) * HD + d] = val * cs + rot * sn;
    } else {
        int nn = n - NQCOLS - NKCOLS;
        int d = nn & 63, hh = nn >> 6;
        g_v[(((size_t)(b * NKV + hh)) * S_LEN + s) * HD + d] = val;
    }
}

// ---------------- flash attention (fp32, online softmax) ---------------------
#define QK_LD 68
#define PS_LD 65
#define ATTN_SMEM_FLOATS (64 * QK_LD * 2 + 64 * PS_LD + 64 * 64 + 3 * 64)

__global__ void __launch_bounds__(256) attn_kernel(
    const float* __restrict__ q, const float* __restrict__ k,
    const float* __restrict__ v, float* __restrict__ ao)
{
    extern __shared__ float smf[];
    float* Qs   = smf;
    float* Ks   = Qs + 64 * QK_LD;
    float* Ps   = Ks + 64 * QK_LD;
    float* Vs   = Ps + 64 * PS_LD;
    float* rowm = Vs + 64 * 64;
    float* rowl = rowm + 64;
    float* corr = rowl + 64;

    const int tid = threadIdx.x;
    const int tx = tid & 15;
    const int ty = tid >> 4;
    const int qb = gridDim.x - 1 - blockIdx.x;
    const int h  = blockIdx.y;
    const int b  = blockIdx.z;
    const int hk = h >> 2;

    const float* qptr  = q + (((size_t)(b * NH + h)) * S_LEN + qb * 64) * HD;
    const float* kbase = k + ((size_t)(b * NKV + hk)) * S_LEN * HD;
    const float* vbase = v + ((size_t)(b * NKV + hk)) * S_LEN * HD;

    const int lrow = tid >> 2;
    const int lc4  = (tid & 3) << 2;

#pragma unroll
    for (int dd = 0; dd < 64; dd += 16) {
        float4 tq = *(const float4*)&qptr[lrow * 64 + dd + lc4];
        int d = dd + lc4;
        Qs[(d + 0) * QK_LD + lrow] = tq.x * 0.125f;
        Qs[(d + 1) * QK_LD + lrow] = tq.y * 0.125f;
        Qs[(d + 2) * QK_LD + lrow] = tq.z * 0.125f;
        Qs[(d + 3) * QK_LD + lrow] = tq.w * 0.125f;
    }
    if (tid < 64) { rowm[tid] = -1e30f; rowl[tid] = 0.f; }

    float o[4][4] = {};

    for (int kb = 0; kb <= qb; kb++) {
        __syncthreads();
        const float* kp = kbase + (size_t)kb * 64 * HD;
        const float* vp = vbase + (size_t)kb * 64 * HD;
#pragma unroll
        for (int dd = 0; dd < 64; dd += 16) {
            float4 tk = *(const float4*)&kp[lrow * 64 + dd + lc4];
            int d = dd + lc4;
            Ks[(d + 0) * QK_LD + lrow] = tk.x;
            Ks[(d + 1) * QK_LD + lrow] = tk.y;
            Ks[(d + 2) * QK_LD + lrow] = tk.z;
            Ks[(d + 3) * QK_LD + lrow] = tk.w;
            float4 tv = *(const float4*)&vp[lrow * 64 + dd + lc4];
            *(float4*)&Vs[lrow * 64 + dd + lc4] = tv;
        }
        __syncthreads();

        float sacc[4][4] = {};
#pragma unroll 16
        for (int d = 0; d < 64; d++) {
            float4 av = *(const float4*)&Qs[d * QK_LD + (ty << 2)];
            float4 bv = *(const float4*)&Ks[d * QK_LD + (tx << 2)];
            float aa[4] = {av.x, av.y, av.z, av.w};
            float bb[4] = {bv.x, bv.y, bv.z, bv.w};
#pragma unroll
            for (int i = 0; i < 4; i++)
#pragma unroll
                for (int j = 0; j < 4; j++)
                    sacc[i][j] += aa[i] * bb[j];
        }
        const bool diag = (kb == qb);
#pragma unroll
        for (int i = 0; i < 4; i++) {
            int r = (ty << 2) + i;
#pragma unroll
            for (int j = 0; j < 4; j++) {
                int c = (tx << 2) + j;
                float sv = sacc[i][j];
                if (diag && c > r) sv = -1e30f;
                Ps[r * PS_LD + c] = sv;
            }
        }
        __syncthreads();

        {
            const int r  = tid >> 2;
            const int c0 = (tid & 3) << 4;
            float rm = -1e30f;
#pragma unroll
            for (int j = 0; j < 16; j++) rm = fmaxf(rm, Ps[r * PS_LD + c0 + j]);
            float mold = rowm[r];
            rm = fmaxf(rm, mold);
            rm = fmaxf(rm, __shfl_xor_sync(0xffffffffu, rm, 1));
            rm = fmaxf(rm, __shfl_xor_sync(0xffffffffu, rm, 2));
            float sum = 0.f;
#pragma unroll
            for (int j = 0; j < 16; j++) {
                float p = __expf(Ps[r * PS_LD + c0 + j] - rm);
                Ps[r * PS_LD + c0 + j] = p;
                sum += p;
            }
            sum += __shfl_xor_sync(0xffffffffu, sum, 1);
            sum += __shfl_xor_sync(0xffffffffu, sum, 2);
            if ((tid & 3) == 0) {
                float co = __expf(mold - rm);
                rowl[r] = rowl[r] * co + sum;
                rowm[r] = rm;
                corr[r] = co;
            }
        }
        __syncthreads();

#pragma unroll
        for (int i = 0; i < 4; i++) {
            float co = corr[(ty << 2) + i];
#pragma unroll
            for (int j = 0; j < 4; j++) o[i][j] *= co;
        }
#pragma unroll 8
        for (int c = 0; c < 64; c++) {
            float4 vv = *(const float4*)&Vs[c * 64 + (tx << 2)];
            float p0 = Ps[((ty << 2) + 0) * PS_LD + c];
            float p1 = Ps[((ty << 2) + 1) * PS_LD + c];
            float p2 = Ps[((ty << 2) + 2) * PS_LD + c];
            float p3 = Ps[((ty << 2) + 3) * PS_LD + c];
            o[0][0] += p0 * vv.x; o[0][1] += p0 * vv.y; o[0][2] += p0 * vv.z; o[0][3] += p0 * vv.w;
            o[1][0] += p1 * vv.x; o[1][1] += p1 * vv.y; o[1][2] += p1 * vv.z; o[1][3] += p1 * vv.w;
            o[2][0] += p2 * vv.x; o[2][1] += p2 * vv.y; o[2][2] += p2 * vv.z; o[2][3] += p2 * vv.w;
            o[3][0] += p3 * vv.x; o[3][1] += p3 * vv.y; o[3][2] += p3 * vv.z; o[3][3] += p3 * vv.w;
        }
    }

#pragma unroll
    for (int i = 0; i < 4; i++) {
        int r = (ty << 2) + i;
        float inv = 1.0f / rowl[r];
        float4 res = make_float4(o[i][0] * inv, o[i][1] * inv, o[i][2] * inv, o[i][3] * inv);
        int s = qb * 64 + r;
        *(float4*)&ao[((size_t)(b * S_LEN + s)) * NQCOLS + h * 64 + (tx << 2)] = res;
    }
}

// ---------------- launch ------------------------------------------------------
extern "C" void kernel_launch(void* const* d_in, const int* in_sizes, int n_in,
                              void* d_out, int out_size)
{
    const float* hidden = (const float*)d_in[0];
    const float* cosp = (const float*)d_in[2];
    const float* sinp = (const float*)d_in[3];
    const float* Wq = (const float*)d_in[4];
    const float* Wk = (const float*)d_in[5];
    const float* Wv = (const float*)d_in[6];
    const float* Wo = (const float*)d_in[7];
    float* out = (float*)d_out;

    float *qkv, *qp, *kp, *vp, *ao;
    bf16 *ahi, *alo, *wqh, *wql, *wkh, *wkl, *wvh, *wvl, *woh, *wol, *aoh, *aol;
    cudaGetSymbolAddress((void**)&qkv, g_qkv);
    cudaGetSymbolAddress((void**)&qp, g_q);
    cudaGetSymbolAddress((void**)&kp, g_k);
    cudaGetSymbolAddress((void**)&vp, g_v);
    cudaGetSymbolAddress((void**)&ao, g_ao);
    cudaGetSymbolAddress((void**)&ahi, g_ahi);
    cudaGetSymbolAddress((void**)&alo, g_alo);
    cudaGetSymbolAddress((void**)&wqh, g_wqhi);
    cudaGetSymbolAddress((void**)&wql, g_wqlo);
    cudaGetSymbolAddress((void**)&wkh, g_wkhi);
    cudaGetSymbolAddress((void**)&wkl, g_wklo);
    cudaGetSymbolAddress((void**)&wvh, g_wvhi);
    cudaGetSymbolAddress((void**)&wvl, g_wvlo);
    cudaGetSymbolAddress((void**)&woh, g_wohi);
    cudaGetSymbolAddress((void**)&wol, g_wolo);
    cudaGetSymbolAddress((void**)&aoh, g_aohi);
    cudaGetSymbolAddress((void**)&aol, g_aolo);

    const int attn_smem = ATTN_SMEM_FLOATS * (int)sizeof(float);
    cudaFuncSetAttribute(attn_kernel, cudaFuncAttributeMaxDynamicSharedMemorySize, attn_smem);
    cudaFuncSetAttribute(gemm_bf16split, cudaFuncAttributeMaxDynamicSharedMemorySize, GEMM_SMEM);

    // operand prep: split hidden, transpose+split weights
    convert_split<<<(M_ROWS * HID / 4 + 255) / 256, 256>>>(hidden, ahi, alo, M_ROWS * HID / 4);
    transpose_split<<<dim3(NQCOLS / 32, HID / 32), dim3(32, 8)>>>(Wq, wqh, wql, HID, NQCOLS);
    transpose_split<<<dim3(NKCOLS / 32, HID / 32), dim3(32, 8)>>>(Wk, wkh, wkl, HID, NKCOLS);
    transpose_split<<<dim3(NKCOLS / 32, HID / 32), dim3(32, 8)>>>(Wv, wvh, wvl, HID, NKCOLS);
    transpose_split<<<dim3(HID / 32, NQCOLS / 32), dim3(32, 8)>>>(Wo, woh, wol, NQCOLS, HID);

    // QKV projections (tensor cores) into fused scratch [4096][3072]
    gemm_bf16split<<<dim3(NQCOLS / 128, M_ROWS / 128), 256, GEMM_SMEM>>>(
        ahi, alo, wqh, wql, qkv, HID, N_TOT);
    gemm_bf16split<<<dim3(NKCOLS / 128, M_ROWS / 128), 256, GEMM_SMEM>>>(
        ahi, alo, wkh, wkl, qkv + NQCOLS, HID, N_TOT);
    gemm_bf16split<<<dim3(NKCOLS / 128, M_ROWS / 128), 256, GEMM_SMEM>>>(
        ahi, alo, wvh, wvl, qkv + NQCOLS + NKCOLS, HID, N_TOT);

    // RoPE + transpose/scatter
    rope_kernel<<<(M_ROWS * N_TOT) / 256, 256>>>(cosp, sinp);

    // causal flash attention (fp32)
    attn_kernel<<<dim3(S_LEN / 64, NH, BATCH), 256, attn_smem>>>(qp, kp, vp, ao);

    // output projection (tensor cores) -> d_out
    convert_split<<<(M_ROWS * NQCOLS / 4 + 255) / 256, 256>>>(ao, aoh, aol, M_ROWS * NQCOLS / 4);
    gemm_bf16split<<<dim3(HID / 128, M_ROWS / 128), 256, GEMM_SMEM>>>(
        aoh, aol, woh, wol, out, NQCOLS, HID);
}

// round 6
// speedup vs baseline: 2.2060x; 1.5316x over previous
#include <cuda_runtime.h>
#include <cuda_bf16.h>
#include <math.h>

#define S_LEN   2048
#define HID     2048
#define NH      32
#define NKV     8
#define HD      64
#define BATCH   2
#define M_ROWS  (BATCH * S_LEN)       // 4096
#define NQCOLS  (NH * HD)             // 2048
#define NKCOLS  (NKV * HD)            // 512
#define N_TOT   (NQCOLS + 2 * NKCOLS) // 3072

typedef __nv_bfloat16 bf16;

// ---------------- scratch ----------------------------------------------------
__device__ float g_qkv[M_ROWS * N_TOT];

__device__ bf16 g_ahi[M_ROWS * HID],   g_alo[M_ROWS * HID];
__device__ bf16 g_wqhi[NQCOLS * HID],  g_wqlo[NQCOLS * HID];
__device__ bf16 g_wkhi[NKCOLS * HID],  g_wklo[NKCOLS * HID];
__device__ bf16 g_wvhi[NKCOLS * HID],  g_wvlo[NKCOLS * HID];
__device__ bf16 g_wohi[HID * NQCOLS],  g_wolo[HID * NQCOLS];
__device__ bf16 g_aohi[M_ROWS * NQCOLS], g_aolo[M_ROWS * NQCOLS];

// attention operands (split bf16)
__device__ bf16 g_qh[BATCH * NH  * S_LEN * HD], g_ql[BATCH * NH  * S_LEN * HD]; // [b][h][s][d], pre-scaled
__device__ bf16 g_kh[BATCH * NKV * S_LEN * HD], g_kl[BATCH * NKV * S_LEN * HD]; // [b][hk][s][d]
__device__ bf16 g_vth[BATCH * NKV * HD * S_LEN], g_vtl[BATCH * NKV * HD * S_LEN]; // [b][hk][d][s]

// ---------------- split conversion -------------------------------------------
__global__ void __launch_bounds__(256) convert_split(
    const float* __restrict__ src, bf16* __restrict__ hi, bf16* __restrict__ lo, int n4)
{
    int i = blockIdx.x * 256 + threadIdx.x;
    if (i >= n4) return;
    float4 v = ((const float4*)src)[i];
    bf16 h0 = __float2bfloat16(v.x), h1 = __float2bfloat16(v.y);
    bf16 h2 = __float2bfloat16(v.z), h3 = __float2bfloat16(v.w);
    bf16 l0 = __float2bfloat16(v.x - __bfloat162float(h0));
    bf16 l1 = __float2bfloat16(v.y - __bfloat162float(h1));
    bf16 l2 = __float2bfloat16(v.z - __bfloat162float(h2));
    bf16 l3 = __float2bfloat16(v.w - __bfloat162float(h3));
    ((__nv_bfloat162*)hi)[2*i]   = __halves2bfloat162(h0, h1);
    ((__nv_bfloat162*)hi)[2*i+1] = __halves2bfloat162(h2, h3);
    ((__nv_bfloat162*)lo)[2*i]   = __halves2bfloat162(l0, l1);
    ((__nv_bfloat162*)lo)[2*i+1] = __halves2bfloat162(l2, l3);
}

// ---------------- transpose + split: W[K][N] fp32 -> T[N][K] bf16 hi/lo ------
__global__ void __launch_bounds__(256) transpose_split(
    const float* __restrict__ W, bf16* __restrict__ Thi, bf16* __restrict__ Tlo,
    int Kdim, int Ndim)
{
    __shared__ float tile[32][33];
    int nx = blockIdx.x * 32, ky = blockIdx.y * 32;
    int tx = threadIdx.x, ty = threadIdx.y;
#pragma unroll
    for (int j = 0; j < 4; j++)
        tile[ty + j*8][tx] = W[(size_t)(ky + ty + j*8) * Ndim + nx + tx];
    __syncthreads();
#pragma unroll
    for (int j = 0; j < 4; j++) {
        float v = tile[tx][ty + j*8];
        bf16 h = __float2bfloat16(v);
        bf16 l = __float2bfloat16(v - __bfloat162float(h));
        size_t o = (size_t)(nx + ty + j*8) * Kdim + ky + tx;
        Thi[o] = h;
        Tlo[o] = l;
    }
}

// ---------------- split-bf16 tensor-core GEMM (validated R5) -----------------
#define GP    40
#define GTILE (128 * GP)

__device__ __forceinline__ void mma_bf16(float* c, const unsigned* a, const unsigned* b) {
    asm volatile(
        "mma.sync.aligned.m16n8k16.row.col.f32.bf16.bf16.f32 "
        "{%0,%1,%2,%3}, {%4,%5,%6,%7}, {%8,%9}, {%0,%1,%2,%3};"
        : "+f"(c[0]), "+f"(c[1]), "+f"(c[2]), "+f"(c[3])
        : "r"(a[0]), "r"(a[1]), "r"(a[2]), "r"(a[3]), "r"(b[0]), "r"(b[1]));
}

__device__ __forceinline__ void cp16(unsigned dst, const void* src) {
    asm volatile("cp.async.cg.shared.global [%0], [%1], 16;" :: "r"(dst), "l"(src));
}

__global__ void __launch_bounds__(256) gemm_bf16split(
    const bf16* __restrict__ Ahi, const bf16* __restrict__ Alo,
    const bf16* __restrict__ Bhi, const bf16* __restrict__ Blo,
    float* __restrict__ C, int K, int ldc)
{
    extern __shared__ bf16 sm[];
    const int tid = threadIdx.x;
    const int m0 = blockIdx.y * 128;
    const int n0 = blockIdx.x * 128;

    const unsigned sbase = (unsigned)__cvta_generic_to_shared(sm);
    const int lrow = tid >> 1;
    const int lq   = (tid & 1) * 16;

    const bf16* gAh = Ahi + (size_t)(m0 + lrow) * K + lq;
    const bf16* gAl = Alo + (size_t)(m0 + lrow) * K + lq;
    const bf16* gBh = Bhi + (size_t)(n0 + lrow) * K + lq;
    const bf16* gBl = Blo + (size_t)(n0 + lrow) * K + lq;
    const unsigned dsm = sbase + (unsigned)(lrow * GP + lq) * 2;
    const unsigned ARR = GTILE * 2;
    const unsigned BUF = 4 * ARR;

    const int lane = tid & 31;
    const int wid  = tid >> 5;
    const int wm = (wid & 1) << 6;
    const int wn = (wid >> 1) << 5;
    const int g = lane >> 2, t = lane & 3;

    float acc[4][4][4];
#pragma unroll
    for (int i = 0; i < 4; i++)
#pragma unroll
        for (int j = 0; j < 4; j++)
#pragma unroll
            for (int r = 0; r < 4; r++) acc[i][j][r] = 0.f;

    const int KT = K >> 5;

    {
        unsigned d = dsm;
        cp16(d + 0*ARR, gAh);      cp16(d + 0*ARR + 16, gAh + 8);
        cp16(d + 1*ARR, gAl);      cp16(d + 1*ARR + 16, gAl + 8);
        cp16(d + 2*ARR, gBh);      cp16(d + 2*ARR + 16, gBh + 8);
        cp16(d + 3*ARR, gBl);      cp16(d + 3*ARR + 16, gBl + 8);
        asm volatile("cp.async.commit_group;");
    }

    for (int kt = 0; kt < KT; kt++) {
        const int buf = kt & 1;
        if (kt + 1 < KT) {
            const int k0 = (kt + 1) << 5;
            unsigned d = dsm + (buf ^ 1) * BUF;
            cp16(d + 0*ARR, gAh + k0);  cp16(d + 0*ARR + 16, gAh + k0 + 8);
            cp16(d + 1*ARR, gAl + k0);  cp16(d + 1*ARR + 16, gAl + k0 + 8);
            cp16(d + 2*ARR, gBh + k0);  cp16(d + 2*ARR + 16, gBh + k0 + 8);
            cp16(d + 3*ARR, gBl + k0);  cp16(d + 3*ARR + 16, gBl + k0 + 8);
            asm volatile("cp.async.commit_group;");
            asm volatile("cp.async.wait_group 1;");
        } else {
            asm volatile("cp.async.wait_group 0;");
        }
        __syncthreads();

        const bf16* sAh = sm + (size_t)buf * 4 * GTILE;
        const bf16* sAl = sAh + GTILE;
        const bf16* sBh = sAl + GTILE;
        const bf16* sBl = sBh + GTILE;

#pragma unroll
        for (int s = 0; s < 2; s++) {
            const int kc = s * 16;
            unsigned ah[4][4], al[4][4];
#pragma unroll
            for (int mt = 0; mt < 4; mt++) {
                const int r = wm + mt * 16;
                ah[mt][0] = *(const unsigned*)&sAh[(r + g    ) * GP + kc + 2*t    ];
                ah[mt][1] = *(const unsigned*)&sAh[(r + g + 8) * GP + kc + 2*t    ];
                ah[mt][2] = *(const unsigned*)&sAh[(r + g    ) * GP + kc + 2*t + 8];
                ah[mt][3] = *(const unsigned*)&sAh[(r + g + 8) * GP + kc + 2*t + 8];
                al[mt][0] = *(const unsigned*)&sAl[(r + g    ) * GP + kc + 2*t    ];
                al[mt][1] = *(const unsigned*)&sAl[(r + g + 8) * GP + kc + 2*t    ];
                al[mt][2] = *(const unsigned*)&sAl[(r + g    ) * GP + kc + 2*t + 8];
                al[mt][3] = *(const unsigned*)&sAl[(r + g + 8) * GP + kc + 2*t + 8];
            }
            unsigned bh[4][2], bl[4][2];
#pragma unroll
            for (int nt = 0; nt < 4; nt++) {
                const int r = wn + nt * 8 + g;
                bh[nt][0] = *(const unsigned*)&sBh[r * GP + kc + 2*t    ];
                bh[nt][1] = *(const unsigned*)&sBh[r * GP + kc + 2*t + 8];
                bl[nt][0] = *(const unsigned*)&sBl[r * GP + kc + 2*t    ];
                bl[nt][1] = *(const unsigned*)&sBl[r * GP + kc + 2*t + 8];
            }
#pragma unroll
            for (int mt = 0; mt < 4; mt++)
#pragma unroll
                for (int nt = 0; nt < 4; nt++) {
                    mma_bf16(acc[mt][nt], ah[mt], bh[nt]);
                    mma_bf16(acc[mt][nt], ah[mt], bl[nt]);
                    mma_bf16(acc[mt][nt], al[mt], bh[nt]);
                }
        }
        __syncthreads();
    }

#pragma unroll
    for (int mt = 0; mt < 4; mt++)
#pragma unroll
        for (int nt = 0; nt < 4; nt++) {
            const int r = m0 + wm + mt * 16 + g;
            const int c = n0 + wn + nt * 8 + 2 * t;
            *(float2*)&C[(size_t)r * ldc + c]       = make_float2(acc[mt][nt][0], acc[mt][nt][1]);
            *(float2*)&C[(size_t)(r + 8) * ldc + c] = make_float2(acc[mt][nt][2], acc[mt][nt][3]);
        }
}

#define GEMM_SMEM (2 * 4 * GTILE * 2)

// ---------------- RoPE -> split-bf16 Q (pre-scaled) & K ----------------------
#define NQK (NQCOLS + NKCOLS)   // 2560
__global__ void __launch_bounds__(256) rope_kernel(
    const float* __restrict__ cosp, const float* __restrict__ sinp)
{
    int idx = blockIdx.x * 256 + threadIdx.x;   // [0, M_ROWS*NQK)
    int m = idx / NQK;
    int n = idx - m * NQK;
    float val = g_qkv[(size_t)m * N_TOT + n];
    float pv  = g_qkv[(size_t)m * N_TOT + (n ^ 32)];
    int b = m >> 11;
    int s = m & (S_LEN - 1);
    int d = n & 63;
    float rot = (d < 32) ? -pv : pv;
    float cs = cosp[(size_t)m * HD + d];
    float sn = sinp[(size_t)m * HD + d];
    float r = val * cs + rot * sn;

    if (n < NQCOLS) {
        int hh = n >> 6;
        r *= 0.125f;                       // 1/sqrt(64) folded into Q
        bf16 h = __float2bfloat16(r);
        bf16 l = __float2bfloat16(r - __bfloat162float(h));
        size_t o = (((size_t)(b * NH + hh)) * S_LEN + s) * HD + d;
        g_qh[o] = h; g_ql[o] = l;
    } else {
        int hh = (n - NQCOLS) >> 6;
        bf16 h = __float2bfloat16(r);
        bf16 l = __float2bfloat16(r - __bfloat162float(h));
        size_t o = (((size_t)(b * NKV + hh)) * S_LEN + s) * HD + d;
        g_kh[o] = h; g_kl[o] = l;
    }
}

// ---------------- V transpose + split: g_qkv v-cols -> [b][hk][d][s] ---------
__global__ void __launch_bounds__(256) vtrans_split()
{
    __shared__ float tile[32][33];
    int s0 = blockIdx.x * 32;
    int dc0 = blockIdx.y * 32;          // 0..480, within 512 v cols
    int b = blockIdx.z;
    int tx = threadIdx.x, ty = threadIdx.y;   // (32,8)
#pragma unroll
    for (int j = 0; j < 4; j++)
        tile[ty + j*8][tx] = g_qkv[(size_t)(b * S_LEN + s0 + ty + j*8) * N_TOT
                                   + NQCOLS + NKCOLS + dc0 + tx];
    __syncthreads();
#pragma unroll
    for (int j = 0; j < 4; j++) {
        float v = tile[tx][ty + j*8];
        int dg = dc0 + ty + j*8;
        int hh = dg >> 6, d = dg & 63;
        bf16 h = __float2bfloat16(v);
        bf16 l = __float2bfloat16(v - __bfloat162float(h));
        size_t o = (((size_t)(b * NKV + hh)) * HD + d) * S_LEN + s0 + tx;
        g_vth[o] = h; g_vtl[o] = l;
    }
}

// ---------------- tensor-core flash attention --------------------------------
// BM=128 rows x BN=64 keys per iter. 8 warps x 16 rows. split-bf16 QK^T and PV.
#define AT_LD 72
#define KVT   (64 * AT_LD)                 // halves per K/V tile
#define ATTN_SMEM ((2 * 128 * AT_LD + 8 * KVT) * 2)   // 110592 bytes

__global__ void __launch_bounds__(256, 1) attn_mma(
    const bf16* __restrict__ qh, const bf16* __restrict__ ql,
    const bf16* __restrict__ kh, const bf16* __restrict__ kl,
    const bf16* __restrict__ vth, const bf16* __restrict__ vtl,
    bf16* __restrict__ aoh, bf16* __restrict__ aol)
{
    extern __shared__ bf16 sb[];
    bf16* sQh = sb;                       // [128][72]
    bf16* sQl = sQh + 128 * AT_LD;
    bf16* sKh = sQl + 128 * AT_LD;        // [2][64][72]
    bf16* sKl = sKh + 2 * KVT;
    bf16* sVh = sKl + 2 * KVT;            // V^T [2][64 d][72 s]
    bf16* sVl = sVh + 2 * KVT;

    const int tid  = threadIdx.x;
    const int lane = tid & 31;
    const int wid  = tid >> 5;
    const int g = lane >> 2, t = lane & 3;
    const int qb = gridDim.x - 1 - blockIdx.x;
    const int h  = blockIdx.y;
    const int b  = blockIdx.z;
    const int hk = h >> 2;
    const int wrow = wid * 16;

    const bf16* qhp = qh + (((size_t)(b * NH + h)) * S_LEN + qb * 128) * HD;
    const bf16* qlp = ql + (((size_t)(b * NH + h)) * S_LEN + qb * 128) * HD;
    const bf16* khp = kh + ((size_t)(b * NKV + hk)) * S_LEN * HD;
    const bf16* klp = kl + ((size_t)(b * NKV + hk)) * S_LEN * HD;
    const bf16* vhp = vth + ((size_t)(b * NKV + hk)) * HD * S_LEN;
    const bf16* vlp = vtl + ((size_t)(b * NKV + hk)) * HD * S_LEN;

    const unsigned uKh = (unsigned)__cvta_generic_to_shared(sKh);
    const unsigned uKl = (unsigned)__cvta_generic_to_shared(sKl);
    const unsigned uVh = (unsigned)__cvta_generic_to_shared(sVh);
    const unsigned uVl = (unsigned)__cvta_generic_to_shared(sVl);

    // load Q (once): 128 rows x 64 halves per array
#pragma unroll
    for (int c = 0; c < 4; c++) {
        int id = tid + c * 256;
        int row = id >> 3, c8 = id & 7;
        *(uint4*)&sQh[row * AT_LD + c8 * 8] = *(const uint4*)&qhp[row * HD + c8 * 8];
        *(uint4*)&sQl[row * AT_LD + c8 * 8] = *(const uint4*)&qlp[row * HD + c8 * 8];
    }

    const int nkb = 2 * qb + 2;

    // prefetch kb=0 into buf 0
    {
#pragma unroll
        for (int c = 0; c < 2; c++) {
            int id = tid + c * 256;
            int row = id >> 3, c8 = id & 7;
            unsigned off = (unsigned)(row * AT_LD + c8 * 8) * 2;
            cp16(uKh + off, khp + (size_t)row * HD + c8 * 8);
            cp16(uKl + off, klp + (size_t)row * HD + c8 * 8);
            cp16(uVh + off, vhp + (size_t)row * S_LEN + c8 * 8);
            cp16(uVl + off, vlp + (size_t)row * S_LEN + c8 * 8);
        }
        asm volatile("cp.async.commit_group;");
    }

    float rm0 = -1e30f, rm1 = -1e30f, l0 = 0.f, l1 = 0.f;
    float o[8][4];
#pragma unroll
    for (int j = 0; j < 8; j++)
#pragma unroll
        for (int e = 0; e < 4; e++) o[j][e] = 0.f;

    const bf16* pQh = sQh + (wrow + g) * AT_LD + 2 * t;
    const bf16* pQl = sQl + (wrow + g) * AT_LD + 2 * t;

    for (int kb = 0; kb < nkb; kb++) {
        const int buf = kb & 1;
        if (kb + 1 < nkb) {
            const unsigned bo = (unsigned)((buf ^ 1) * KVT) * 2;
            const size_t ks = (size_t)(kb + 1) * 64;
#pragma unroll
            for (int c = 0; c < 2; c++) {
                int id = tid + c * 256;
                int row = id >> 3, c8 = id & 7;
                unsigned off = bo + (unsigned)(row * AT_LD + c8 * 8) * 2;
                cp16(uKh + off, khp + (ks + row) * HD + c8 * 8);
                cp16(uKl + off, klp + (ks + row) * HD + c8 * 8);
                cp16(uVh + off, vhp + (size_t)row * S_LEN + ks + c8 * 8);
                cp16(uVl + off, vlp + (size_t)row * S_LEN + ks + c8 * 8);
            }
            asm volatile("cp.async.commit_group;");
            asm volatile("cp.async.wait_group 1;");
        } else {
            asm volatile("cp.async.wait_group 0;");
        }
        __syncthreads();   // data ready (and Q ready on iter 0)

        const bf16* pKh = sKh + buf * KVT + g * AT_LD + 2 * t;
        const bf16* pKl = sKl + buf * KVT + g * AT_LD + 2 * t;

        // ---- S = (Q/8) K^T, split-bf16 (3 mma) ----
        float s[8][4];
#pragma unroll
        for (int j = 0; j < 8; j++)
#pragma unroll
            for (int e = 0; e < 4; e++) s[j][e] = 0.f;

#pragma unroll
        for (int kt = 0; kt < 4; kt++) {
            const int kc = kt * 16;
            unsigned ah[4], al[4];
            ah[0] = *(const unsigned*)&pQh[kc];
            ah[1] = *(const unsigned*)&pQh[8 * AT_LD + kc];
            ah[2] = *(const unsigned*)&pQh[kc + 8];
            ah[3] = *(const unsigned*)&pQh[8 * AT_LD + kc + 8];
            al[0] = *(const unsigned*)&pQl[kc];
            al[1] = *(const unsigned*)&pQl[8 * AT_LD + kc];
            al[2] = *(const unsigned*)&pQl[kc + 8];
            al[3] = *(const unsigned*)&pQl[8 * AT_LD + kc + 8];
#pragma unroll
            for (int j = 0; j < 8; j++) {
                unsigned bh[2], bl[2];
                bh[0] = *(const unsigned*)&pKh[j * 8 * AT_LD + kc];
                bh[1] = *(const unsigned*)&pKh[j * 8 * AT_LD + kc + 8];
                bl[0] = *(const unsigned*)&pKl[j * 8 * AT_LD + kc];
                bl[1] = *(const unsigned*)&pKl[j * 8 * AT_LD + kc + 8];
                mma_bf16(s[j], ah, bh);
                mma_bf16(s[j], ah, bl);
                mma_bf16(s[j], al, bh);
            }
        }

        // ---- causal mask (only possible on kb >= 2*qb) ----
        if (kb >= 2 * qb) {
            const int r0 = qb * 128 + wrow + g;
            const int cb = kb * 64 + 2 * t;
#pragma unroll
            for (int j = 0; j < 8; j++) {
                const int c = cb + j * 8;
                if (c     > r0)     s[j][0] = -1e30f;
                if (c + 1 > r0)     s[j][1] = -1e30f;
                if (c     > r0 + 8) s[j][2] = -1e30f;
                if (c + 1 > r0 + 8) s[j][3] = -1e30f;
            }
        }

        // ---- online softmax (rows g, g+8 of this warp) ----
        float m0 = rm0, m1 = rm1;
#pragma unroll
        for (int j = 0; j < 8; j++) {
            m0 = fmaxf(m0, fmaxf(s[j][0], s[j][1]));
            m1 = fmaxf(m1, fmaxf(s[j][2], s[j][3]));
        }
        m0 = fmaxf(m0, __shfl_xor_sync(0xffffffffu, m0, 1));
        m0 = fmaxf(m0, __shfl_xor_sync(0xffffffffu, m0, 2));
        m1 = fmaxf(m1, __shfl_xor_sync(0xffffffffu, m1, 1));
        m1 = fmaxf(m1, __shfl_xor_sync(0xffffffffu, m1, 2));
        const float c0 = __expf(rm0 - m0);
        const float c1 = __expf(rm1 - m1);
        rm0 = m0; rm1 = m1;

        float sum0 = 0.f, sum1 = 0.f;
        unsigned ph[4][4], pl[4][4];
#pragma unroll
        for (int j = 0; j < 8; j++) {
            float p0 = __expf(s[j][0] - m0);
            float p1 = __expf(s[j][1] - m0);
            float p2 = __expf(s[j][2] - m1);
            float p3 = __expf(s[j][3] - m1);
            sum0 += p0 + p1;
            sum1 += p2 + p3;
            __nv_bfloat162 h01 = __floats2bfloat162_rn(p0, p1);
            __nv_bfloat162 h23 = __floats2bfloat162_rn(p2, p3);
            float r0 = p0 - __bfloat162float(__low2bfloat16(h01));
            float r1 = p1 - __bfloat162float(__high2bfloat16(h01));
            float r2 = p2 - __bfloat162float(__low2bfloat16(h23));
            float r3 = p3 - __bfloat162float(__high2bfloat16(h23));
            __nv_bfloat162 q01 = __floats2bfloat162_rn(r0, r1);
            __nv_bfloat162 q23 = __floats2bfloat162_rn(r2, r3);
            const int kt = j >> 1, hf = (j & 1) << 1;
            ph[kt][hf    ] = *(unsigned*)&h01;
            ph[kt][hf + 1] = *(unsigned*)&h23;
            pl[kt][hf    ] = *(unsigned*)&q01;
            pl[kt][hf + 1] = *(unsigned*)&q23;
        }
        sum0 += __shfl_xor_sync(0xffffffffu, sum0, 1);
        sum0 += __shfl_xor_sync(0xffffffffu, sum0, 2);
        sum1 += __shfl_xor_sync(0xffffffffu, sum1, 1);
        sum1 += __shfl_xor_sync(0xffffffffu, sum1, 2);
        l0 = l0 * c0 + sum0;
        l1 = l1 * c1 + sum1;

#pragma unroll
        for (int j = 0; j < 8; j++) {
            o[j][0] *= c0; o[j][1] *= c0;
            o[j][2] *= c1; o[j][3] *= c1;
        }

        // ---- O += P V  (P split in-register, V split in smem) ----
        const bf16* pVh = sVh + buf * KVT + g * AT_LD + 2 * t;
        const bf16* pVl = sVl + buf * KVT + g * AT_LD + 2 * t;
#pragma unroll
        for (int kt = 0; kt < 4; kt++) {
            const int kc = kt * 16;
#pragma unroll
            for (int j = 0; j < 8; j++) {
                unsigned bh[2], bl[2];
                bh[0] = *(const unsigned*)&pVh[j * 8 * AT_LD + kc];
                bh[1] = *(const unsigned*)&pVh[j * 8 * AT_LD + kc + 8];
                bl[0] = *(const unsigned*)&pVl[j * 8 * AT_LD + kc];
                bl[1] = *(const unsigned*)&pVl[j * 8 * AT_LD + kc + 8];
                mma_bf16(o[j], ph[kt], bh);
                mma_bf16(o[j], ph[kt], bl);
                mma_bf16(o[j], pl[kt], bh);
            }
        }
        __syncthreads();   // all warps done reading this buf before it is refilled
    }

    // ---- epilogue: normalize, split to bf16 hi/lo, write [b*s][h*64+d] ------
    const float inv0 = 1.0f / l0;
    const float inv1 = 1.0f / l1;
    const int r0 = qb * 128 + wrow + g;
#pragma unroll
    for (int j = 0; j < 8; j++) {
        const int c = h * 64 + j * 8 + 2 * t;
        float v0 = o[j][0] * inv0, v1 = o[j][1] * inv0;
        float v2 = o[j][2] * inv1, v3 = o[j][3] * inv1;
        __nv_bfloat162 h01 = __floats2bfloat162_rn(v0, v1);
        __nv_bfloat162 h23 = __floats2bfloat162_rn(v2, v3);
        __nv_bfloat162 q01 = __floats2bfloat162_rn(
            v0 - __bfloat162float(__low2bfloat16(h01)),
            v1 - __bfloat162float(__high2bfloat16(h01)));
        __nv_bfloat162 q23 = __floats2bfloat162_rn(
            v2 - __bfloat162float(__low2bfloat16(h23)),
            v3 - __bfloat162float(__high2bfloat16(h23)));
        size_t o0 = (size_t)(b * S_LEN + r0) * NQCOLS + c;
        size_t o1 = (size_t)(b * S_LEN + r0 + 8) * NQCOLS + c;
        *(__nv_bfloat162*)&aoh[o0] = h01;
        *(__nv_bfloat162*)&aol[o0] = q01;
        *(__nv_bfloat162*)&aoh[o1] = h23;
        *(__nv_bfloat162*)&aol[o1] = q23;
    }
}

// ---------------- launch ------------------------------------------------------
extern "C" void kernel_launch(void* const* d_in, const int* in_sizes, int n_in,
                              void* d_out, int out_size)
{
    const float* hidden = (const float*)d_in[0];
    const float* cosp = (const float*)d_in[2];
    const float* sinp = (const float*)d_in[3];
    const float* Wq = (const float*)d_in[4];
    const float* Wk = (const float*)d_in[5];
    const float* Wv = (const float*)d_in[6];
    const float* Wo = (const float*)d_in[7];
    float* out = (float*)d_out;

    float *qkv;
    bf16 *ahi, *alo, *wqh, *wql, *wkh, *wkl, *wvh, *wvl, *woh, *wol, *aoh, *aol;
    bf16 *qh, *ql, *kh, *kl, *vth, *vtl;
    cudaGetSymbolAddress((void**)&qkv, g_qkv);
    cudaGetSymbolAddress((void**)&ahi, g_ahi);
    cudaGetSymbolAddress((void**)&alo, g_alo);
    cudaGetSymbolAddress((void**)&wqh, g_wqhi);
    cudaGetSymbolAddress((void**)&wql, g_wqlo);
    cudaGetSymbolAddress((void**)&wkh, g_wkhi);
    cudaGetSymbolAddress((void**)&wkl, g_wklo);
    cudaGetSymbolAddress((void**)&wvh, g_wvhi);
    cudaGetSymbolAddress((void**)&wvl, g_wvlo);
    cudaGetSymbolAddress((void**)&woh, g_wohi);
    cudaGetSymbolAddress((void**)&wol, g_wolo);
    cudaGetSymbolAddress((void**)&aoh, g_aohi);
    cudaGetSymbolAddress((void**)&aol, g_aolo);
    cudaGetSymbolAddress((void**)&qh, g_qh);
    cudaGetSymbolAddress((void**)&ql, g_ql);
    cudaGetSymbolAddress((void**)&kh, g_kh);
    cudaGetSymbolAddress((void**)&kl, g_kl);
    cudaGetSymbolAddress((void**)&vth, g_vth);
    cudaGetSymbolAddress((void**)&vtl, g_vtl);

    cudaFuncSetAttribute(gemm_bf16split, cudaFuncAttributeMaxDynamicSharedMemorySize, GEMM_SMEM);
    cudaFuncSetAttribute(attn_mma, cudaFuncAttributeMaxDynamicSharedMemorySize, ATTN_SMEM);

    // operand prep
    convert_split<<<(M_ROWS * HID / 4 + 255) / 256, 256>>>(hidden, ahi, alo, M_ROWS * HID / 4);
    transpose_split<<<dim3(NQCOLS / 32, HID / 32), dim3(32, 8)>>>(Wq, wqh, wql, HID, NQCOLS);
    transpose_split<<<dim3(NKCOLS / 32, HID / 32), dim3(32, 8)>>>(Wk, wkh, wkl, HID, NKCOLS);
    transpose_split<<<dim3(NKCOLS / 32, HID / 32), dim3(32, 8)>>>(Wv, wvh, wvl, HID, NKCOLS);
    transpose_split<<<dim3(HID / 32, NQCOLS / 32), dim3(32, 8)>>>(Wo, woh, wol, NQCOLS, HID);

    // QKV projections into fused scratch [4096][3072]
    gemm_bf16split<<<dim3(NQCOLS / 128, M_ROWS / 128), 256, GEMM_SMEM>>>(
        ahi, alo, wqh, wql, qkv, HID, N_TOT);
    gemm_bf16split<<<dim3(NKCOLS / 128, M_ROWS / 128), 256, GEMM_SMEM>>>(
        ahi, alo, wkh, wkl, qkv + NQCOLS, HID, N_TOT);
    gemm_bf16split<<<dim3(NKCOLS / 128, M_ROWS / 128), 256, GEMM_SMEM>>>(
        ahi, alo, wvh, wvl, qkv + NQCOLS + NKCOLS, HID, N_TOT);

    // RoPE -> split Q/K ; V transpose -> split V^T
    rope_kernel<<<(M_ROWS * NQK) / 256, 256>>>(cosp, sinp);
    vtrans_split<<<dim3(S_LEN / 32, NKCOLS / 32, BATCH), dim3(32, 8)>>>();

    // tensor-core causal flash attention -> split bf16 attention output
    attn_mma<<<dim3(S_LEN / 128, NH, BATCH), 256, ATTN_SMEM>>>(
        qh, ql, kh, kl, vth, vtl, aoh, aol);

    // output projection -> d_out
    gemm_bf16split<<<dim3(HID / 128, M_ROWS / 128), 256, GEMM_SMEM>>>(
        aoh, aol, woh, wol, out, NQCOLS, HID);
}